// round 17
// baseline (speedup 1.0000x reference)
#include <cuda_runtime.h>
#include <cuda_fp16.h>
#include <math.h>

#define NB 16
#define NH 16
#define NHD 64
#define ND 1024
#define NL 513
#define NP 1024

#define NX4   2101248   // x      8208*1024 /4
#define NQW4   786432   // qkv_w  3072*1024 /4
#define NPW4   262144   // pos_w  1024*1024 /4
#define NPE4  4194304   // pe     16*16*64*1024 /4
#define NOW4   262144   // out_w  1024*1024 /4

// Scratch (allocation-free rule: __device__ globals). fp16 everywhere.
__device__ __half g_Xh [NX4*4];
__device__ __half g_QWh[NQW4*4];
__device__ __half g_PWh[NPW4*4];
__device__ __half g_PEh[NPE4*4];
__device__ __half g_OWh[NOW4*4];
__device__ __half g_QCh[NB*NH*NL*NHD];   // q + content_bias
__device__ __half g_QPh[NB*NH*NL*NHD];   // q + position_bias
__device__ __half g_Kh [NB*NH*NL*NHD];
__device__ __half g_Vh [NB*NH*NL*NHD];
__device__ __half g_PTh[NB*NH*NP*NHD];
__device__ __half g_CTXh[NB*NL*ND];      // attention output (fp16)

__device__ __forceinline__ void mma_f16(float* d, const uint4& a, const uint2& b) {
    asm volatile(
        "mma.sync.aligned.m16n8k16.row.col.f32.f16.f16.f32 "
        "{%0,%1,%2,%3}, {%4,%5,%6,%7}, {%8,%9}, {%0,%1,%2,%3};"
        : "+f"(d[0]), "+f"(d[1]), "+f"(d[2]), "+f"(d[3])
        : "r"(a.x), "r"(a.y), "r"(a.z), "r"(a.w), "r"(b.x), "r"(b.y));
}

__device__ __forceinline__ void ldsm_x4(uint4& d, const unsigned* p) {
    unsigned a = (unsigned)__cvta_generic_to_shared((void*)p);
    asm volatile("ldmatrix.sync.aligned.m8n8.x4.shared.b16 {%0,%1,%2,%3}, [%4];"
                 : "=r"(d.x), "=r"(d.y), "=r"(d.z), "=r"(d.w) : "r"(a));
}
__device__ __forceinline__ void ldsm_x2(uint2& d, const unsigned* p) {
    unsigned a = (unsigned)__cvta_generic_to_shared((void*)p);
    asm volatile("ldmatrix.sync.aligned.m8n8.x2.shared.b16 {%0,%1}, [%2];"
                 : "=r"(d.x), "=r"(d.y) : "r"(a));
}
__device__ __forceinline__ void cpa16(unsigned daddr, const void* g, int sz) {
    asm volatile("cp.async.ca.shared.global [%0], [%1], 16, %2;"
                 :: "r"(daddr), "l"(g), "r"(sz));
}
#define CP_COMMIT() asm volatile("cp.async.commit_group;")
#define CP_WAIT2()  asm volatile("cp.async.wait_group 2;")

__device__ __forceinline__ unsigned pkh2f(float x, float y) {
    __half2 h = __floats2half2_rn(x, y);
    return *(unsigned*)&h;
}
__device__ __forceinline__ unsigned pkhh(__half x, __half y) {
    __half2 h = __halves2half2(x, y);
    return *(unsigned*)&h;
}

// ---------------------------------------------------------------------------
// One-shot fp32 -> fp16 conversion (streaming, bandwidth-bound).
// ---------------------------------------------------------------------------
__global__ void cvt_all(const float* __restrict__ x, const float* __restrict__ qw,
                        const float* __restrict__ pw, const float* __restrict__ pe,
                        const float* __restrict__ ow)
{
    int tid = blockIdx.x * blockDim.x + threadIdx.x;
    int stride = gridDim.x * blockDim.x;
#define CVT(SRC, DST, N4)                                    \
    for (int i = tid; i < (N4); i += stride) {               \
        float4 v = ((const float4*)(SRC))[i];                \
        uint2 o;                                             \
        o.x = pkh2f(v.x, v.y); o.y = pkh2f(v.z, v.w);        \
        ((uint2*)(DST))[i] = o;                              \
    }
    CVT(x,  g_Xh,  NX4)
    CVT(qw, g_QWh, NQW4)
    CVT(pw, g_PWh, NPW4)
    CVT(pe, g_PEh, NPE4)
    CVT(ow, g_OWh, NOW4)
#undef CVT
}

// ---------------------------------------------------------------------------
// GEMM mainloop: cp.async row-major staging (80B-pitch rows) + ldmatrix
// fragments (mapping verified in R11), 4-stage ring, 2-chunk lookahead, ONE
// barrier per chunk. EPI 0 = QKV scatter, 1 = POS, 2 = OUT.
// Dynamic smem 81,920 B (4 x (2560+2560) uints).
// ---------------------------------------------------------------------------
template<int EPI>
__device__ __forceinline__ void gemm_body(
    const __half* __restrict__ A, const __half* __restrict__ Bw,
    int M, int m0, int n0,
    const float* __restrict__ bias,
    const float* __restrict__ cbias, const float* __restrict__ pbias,
    float* __restrict__ out)
{
    const int K = 1024;
    extern __shared__ unsigned gsm[];
    unsigned* sA = gsm;             // 4 x 2560 uints (128 rows x 20)
    unsigned* sB = gsm + 4 * 2560;  // 4 x 2560

    int t = threadIdx.x, lane = t & 31, w = t >> 5;
    int warpM = w & 1, warpN = w >> 1;

    int rs = t >> 1;            // staging row 0..127
    int hs = (t & 1) * 16;      // halves offset within 32-wide chunk
    unsigned sAb = (unsigned)__cvta_generic_to_shared(sA) + (rs * 20 + (hs >> 1)) * 4;
    unsigned sBb = (unsigned)__cvta_generic_to_shared(sB) + (rs * 20 + (hs >> 1)) * 4;

    unsigned aOff = (warpM * 64 + ((lane >> 3) & 1) * 8 + (lane & 7)) * 20 + (lane >> 4) * 4;
    unsigned bOff = (warpN * 32 + (lane & 7)) * 20 + ((lane >> 3) & 1) * 4;

    float acc[4][4][4];
#pragma unroll
    for (int i = 0; i < 4; i++)
#pragma unroll
        for (int j = 0; j < 4; j++)
#pragma unroll
            for (int r = 0; r < 4; r++) acc[i][j][r] = 0.f;

#define CPA(BUF, KT) {                                                       \
        int gm = m0 + rs;                                                    \
        int ok = gm < M;                                                     \
        int gmc = ok ? gm : (M - 1);                                         \
        int sz = ok ? 16 : 0;                                                \
        const __half* gA = A + (size_t)gmc * K + (KT) + hs;                  \
        unsigned da = sAb + (BUF) * 10240;                                   \
        cpa16(da, gA, sz); cpa16(da + 16, gA + 8, sz);                       \
        const __half* gB = Bw + (size_t)(n0 + rs) * K + (KT) + hs;           \
        unsigned db = sBb + (BUF) * 10240;                                   \
        cpa16(db, gB, 16); cpa16(db + 16, gB + 8, 16);                       \
    }

    CPA(0, 0);  CP_COMMIT();
    CPA(1, 32); CP_COMMIT();

    for (int c = 0; c < 32; c++) {
        if (c + 2 < 32) { CPA((c + 2) & 3, (c + 2) * 32); }
        CP_COMMIT();
        CP_WAIT2();
        __syncthreads();
        unsigned base = (c & 3) * 2560;
#pragma unroll
        for (int s = 0; s < 2; s++) {
            uint4 av[4];
            uint2 bv[4];
#pragma unroll
            for (int i = 0; i < 4; i++)
                ldsm_x4(av[i], &sA[base + aOff + i * 320 + s * 8]);
#pragma unroll
            for (int j = 0; j < 4; j++)
                ldsm_x2(bv[j], &sB[base + bOff + j * 160 + s * 8]);
#pragma unroll
            for (int i = 0; i < 4; i++)
#pragma unroll
                for (int j = 0; j < 4; j++)
                    mma_f16(acc[i][j], av[i], bv[j]);
        }
    }
#undef CPA

    int mb = m0 + warpM * 64 + (lane >> 2);
    int nb = n0 + warpN * 32 + (lane & 3) * 2;
#pragma unroll
    for (int i = 0; i < 4; i++) {
#pragma unroll
        for (int rr = 0; rr < 2; rr++) {
            int m = mb + i * 16 + rr * 8;
            if (m >= M) continue;
            if (EPI == 0) {
                int b_ = m / NL, l = m - b_ * NL;
#pragma unroll
                for (int j = 0; j < 4; j++) {
                    int n = nb + j * 8;
                    float v0 = acc[i][j][rr * 2 + 0] + bias[n];
                    float v1 = acc[i][j][rr * 2 + 1] + bias[n + 1];
                    int part = n >> 10, c1 = n & 1023;
                    int hh = c1 >> 6, hd = c1 & 63;
                    size_t o = ((((size_t)b_ * NH + hh) * NL + l) << 6) + hd;
                    if (part == 0) {
                        *(unsigned*)&g_QCh[o] = pkh2f(v0 + cbias[c1], v1 + cbias[c1 + 1]);
                        *(unsigned*)&g_QPh[o] = pkh2f(v0 + pbias[c1], v1 + pbias[c1 + 1]);
                    } else if (part == 1) {
                        *(unsigned*)&g_Kh[o] = pkh2f(v0, v1);
                    } else {
                        *(unsigned*)&g_Vh[o] = pkh2f(v0, v1);
                    }
                }
            } else if (EPI == 1) {
                float bm = bias[m];
#pragma unroll
                for (int j = 0; j < 4; j++) {
                    int n = nb + j * 8;
                    float v0 = acc[i][j][rr * 2 + 0] + bm;
                    float v1 = acc[i][j][rr * 2 + 1] + bm;
                    int bh = n >> 6, hd = n & 63;
                    *(unsigned*)&g_PTh[((((size_t)bh) << 10) + m) * 64 + hd] = pkh2f(v0, v1);
                }
            } else {
#pragma unroll
                for (int j = 0; j < 4; j++) {
                    int n = nb + j * 8;
                    float2 st;
                    st.x = acc[i][j][rr * 2 + 0] + bias[n];
                    st.y = acc[i][j][rr * 2 + 1] + bias[n + 1];
                    *(float2*)(out + (size_t)m * ND + n) = st;
                }
            }
        }
    }
}

// Fused QKV (bids 0..1559) + POS (1560..2583) projections in one grid.
__global__ void __launch_bounds__(256, 2)
gemm_fused(const float* __restrict__ qb, const float* __restrict__ cb,
           const float* __restrict__ pbv, const float* __restrict__ posb)
{
    int bid = blockIdx.x;
    if (bid < 1560) {
        gemm_body<0>(g_Xh, g_QWh, NB * NL, (bid / 24) * 128, (bid % 24) * 128,
                     qb, cb, pbv, nullptr);
    } else {
        int i2 = bid - 1560;
        gemm_body<1>(g_PWh, g_PEh, 1024, (i2 % 8) * 128, (i2 / 8) * 128,
                     posb, nullptr, nullptr, nullptr);
    }
}

// Output projection.
__global__ void __launch_bounds__(256, 2)
gemm_out(int M, const float* __restrict__ bias, float* __restrict__ out)
{
    gemm_body<2>(g_CTXh, g_OWh, M, blockIdx.y * 128, blockIdx.x * 128,
                 bias, nullptr, nullptr, out);
}

// ---------------------------------------------------------------------------
// Flash-style fused attention (R16 passing config; ctx stored fp16).
// CTA = 64 q x (b,h); 8 warps: rg=w&3 rows, ch=w>>2 key-chunk.
// Dynamic smem 49,664 B -> 2 CTAs/SM.
// ---------------------------------------------------------------------------
__global__ void __launch_bounds__(256, 2)
attn_flash(const unsigned char* __restrict__ mask, __half* __restrict__ ctx)
{
    extern __shared__ unsigned smu[];
    unsigned* sK = smu;                 // 2080 uints (4 x 520)
    unsigned* sV = smu + 2080;          // 2080 uints
    unsigned* sP = smu + 4160;          // 4096 uints (4 x 1024)
    __half*   sG = (__half*)(smu + 8256); // 64 x 130 halves (4160 uints)
    float* mO  = (float*)smu;           // merge overlay [64][68]
    float* mml = (float*)smu + 64 * 68; // [64][2]

    const float NEG = -3.4028235e38f;
    int t = threadIdx.x, lam = t & 31, w = t >> 5;
    int rg = w & 3, ch = w >> 2;
    int it = blockIdx.x, h = blockIdx.y, b = blockIdx.z;
    int i0 = it * 64;
    size_t bh = (size_t)b * NH + h;
    const __half* QCg = g_QCh + bh * NL * NHD;
    const __half* QPg = g_QPh + bh * NL * NHD;
    const __half* Kg  = g_Kh  + bh * NL * NHD;
    const __half* Vg  = g_Vh  + bh * NL * NHD;
    const __half* Pg  = g_PTh + bh * NP * NHD;

    int gr0 = rg * 16 + (lam >> 2);
    int r0g = i0 + gr0, r1g = r0g + 8;
    int gt0 = 6 - 2 * rg;
    int vkey = t >> 4;
    int vhd4 = (t & 15) * 4;
    int la2  = (lam & 3) * 2;

    const unsigned char* mrow0 = mask + ((size_t)b * NL + (r0g < NL ? r0g : NL - 1)) * NL;
    const unsigned char* mrow1 = mask + ((size_t)b * NL + (r1g < NL ? r1g : NL - 1)) * NL;

    // Q frags, prescaled by 1/8 (exact power of 2)
    __half2 hsc = __float2half2_rn(0.125f);
    uint4 qcf[4], qpf[4];
#pragma unroll
    for (int s = 0; s < 4; s++) {
        int c0 = s * 16 + la2;
        __half2 v;
        unsigned r[8] = {0,0,0,0,0,0,0,0};
        if (r0g < NL) {
            v = __hmul2(*(const __half2*)(QCg + r0g * 64 + c0), hsc);     r[0] = *(unsigned*)&v;
            v = __hmul2(*(const __half2*)(QCg + r0g * 64 + c0 + 8), hsc); r[2] = *(unsigned*)&v;
            v = __hmul2(*(const __half2*)(QPg + r0g * 64 + c0), hsc);     r[4] = *(unsigned*)&v;
            v = __hmul2(*(const __half2*)(QPg + r0g * 64 + c0 + 8), hsc); r[6] = *(unsigned*)&v;
        }
        if (r1g < NL) {
            v = __hmul2(*(const __half2*)(QCg + r1g * 64 + c0), hsc);     r[1] = *(unsigned*)&v;
            v = __hmul2(*(const __half2*)(QCg + r1g * 64 + c0 + 8), hsc); r[3] = *(unsigned*)&v;
            v = __hmul2(*(const __half2*)(QPg + r1g * 64 + c0), hsc);     r[5] = *(unsigned*)&v;
            v = __hmul2(*(const __half2*)(QPg + r1g * 64 + c0 + 8), hsc); r[7] = *(unsigned*)&v;
        }
        qcf[s] = make_uint4(r[0], r[1], r[2], r[3]);
        qpf[s] = make_uint4(r[4], r[5], r[6], r[7]);
    }

    float O[8][4];
#pragma unroll
    for (int n = 0; n < 8; n++)
#pragma unroll
        for (int r = 0; r < 4; r++) O[n][r] = 0.f;
    float m0 = NEG, m1 = NEG, l0 = 0.f, l1 = 0.f;

    for (int jt = 0; jt < 9; jt++) {
        int j0 = jt * 64;
        int xorv = (jt & 1) << 3;
        __syncthreads();   // staging writes vs all prev-jt reads (K,V,P,G)

        // ---- stage K tile (B-frags, k=hd, n=key) ----
        {
            int step = vhd4 >> 4, k16 = vhd4 & 15;
            unsigned boff = step * 520 + ((k16 & 7) >> 1) * 2 + (k16 >> 3);
#pragma unroll
            for (int u = 0; u < 4; u++) {
                int key = vkey + u * 16;
                int gk = j0 + key;
                uint2 kv = make_uint2(0u, 0u);
                if (gk < NL) kv = *(const uint2*)(Kg + (size_t)gk * 64 + vhd4);
                unsigned base = boff + (key >> 3) * 64 + (key & 7) * 8;
                sK[base]     = kv.x;
                sK[base + 2] = kv.y;
            }
        }
        // ---- stage V tile (B-frags, k=key, n=hd); rotated store order ----
#pragma unroll
        for (int u = 0; u < 2; u++) {
            int k0 = 2 * vkey + 32 * u;
            int gk = j0 + k0;
            uint2 a = (gk < NL)     ? *(const uint2*)(Vg + (size_t)gk * 64 + vhd4)       : make_uint2(0u, 0u);
            uint2 bq = (gk + 1 < NL) ? *(const uint2*)(Vg + (size_t)(gk + 1) * 64 + vhd4) : make_uint2(0u, 0u);
            __half2 a01 = *(__half2*)&a.x,  a23 = *(__half2*)&a.y;
            __half2 b01 = *(__half2*)&bq.x, b23 = *(__half2*)&bq.y;
            unsigned o0 = pkhh(a01.x, b01.x);
            unsigned o1 = pkhh(a01.y, b01.y);
            unsigned o2 = pkhh(a23.x, b23.x);
            unsigned o3 = pkhh(a23.y, b23.y);
            int step = k0 >> 4, kk = k0 & 15;
            unsigned koff = step * 520 + ((kk & 7) >> 1) * 2 + (kk >> 3)
                          + (vhd4 >> 3) * 64 + (vhd4 & 4) * 8;
            int rot = lam & 3;
#pragma unroll
            for (int e4 = 0; e4 < 4; e4++) {
                int e = (e4 + rot) & 3;
                unsigned v = (e == 0) ? o0 : (e == 1) ? o1 : (e == 2) ? o2 : o3;
                sV[koff + e * 8] = v;
            }
        }
        // ---- stage P band (circular: full 128 rows at jt=0, 64 new after) ----
        int pbase = j0 - i0 + 449;
        if (jt == 0) {
#pragma unroll
            for (int u = 0; u < 8; u++) {
                int idx = u * 256 + t;
                int c = idx >> 4, d4 = (idx & 15) * 4;
                int p = pbase + c;
                uint2 pv = make_uint2(0u, 0u);
                if ((unsigned)p < (unsigned)NP)
                    pv = *(const uint2*)(Pg + (size_t)p * 64 + d4);
                int step = d4 >> 4, k16 = d4 & 15;
                unsigned a0 = step * 1024 + (c >> 3) * 64 + ((c & 7) * 4 + ((k16 & 7) >> 1)) * 2 + (k16 >> 3);
                sP[a0]     = pv.x;
                sP[a0 + 2] = pv.y;
            }
        } else {
#pragma unroll
            for (int u = 0; u < 4; u++) {
                int idx = u * 256 + t;
                int c = 64 + (idx >> 4), d4 = (idx & 15) * 4;
                int p = pbase + c;
                uint2 pv = make_uint2(0u, 0u);
                if ((unsigned)p < (unsigned)NP)
                    pv = *(const uint2*)(Pg + (size_t)p * 64 + d4);
                int step = d4 >> 4, k16 = d4 & 15;
                unsigned a0 = step * 1024 + ((c >> 3) ^ xorv) * 64 + ((c & 7) * 4 + ((k16 & 7) >> 1)) * 2 + (k16 >> 3);
                sP[a0]     = pv.x;
                sP[a0 + 2] = pv.y;
            }
        }
        __syncthreads();

        // ---- content MMA ----
        float C[4][4];
#pragma unroll
        for (int nt = 0; nt < 4; nt++)
#pragma unroll
            for (int r = 0; r < 4; r++) C[nt][r] = 0.f;
#pragma unroll
        for (int s = 0; s < 4; s++) {
#pragma unroll
            for (int nt = 0; nt < 4; nt++) {
                uint2 bv = *(const uint2*)&sK[s * 520 + (ch * 4 + nt) * 64 + lam * 2];
                mma_f16(C[nt], qcf[s], bv);
            }
        }
        // ---- G MMA (band-pruned) + store ----
        {
            float G[5][4];
#pragma unroll
            for (int nt = 0; nt < 5; nt++)
#pragma unroll
                for (int r = 0; r < 4; r++) G[nt][r] = 0.f;
#pragma unroll
            for (int s = 0; s < 4; s++) {
#pragma unroll
                for (int nt = 0; nt < 5; nt++) {
                    int tg = (gt0 + ch * 5 + nt) ^ xorv;
                    uint2 bv = *(const uint2*)&sP[s * 1024 + tg * 64 + lam * 2];
                    mma_f16(G[nt], qpf[s], bv);
                }
            }
#pragma unroll
            for (int nt = 0; nt < 5; nt++) {
                int c0 = (gt0 + ch * 5 + nt) * 8 + la2;
                *(__half2*)&sG[gr0 * 130 + c0]       = __floats2half2_rn(G[nt][0], G[nt][1]);
                *(__half2*)&sG[(gr0 + 8) * 130 + c0] = __floats2half2_rn(G[nt][2], G[nt][3]);
            }
        }
        __syncthreads();   // G visible to both ch warps

        // ---- gather + mask -> masked scaled scores in C ----
        float mt0 = NEG, mt1 = NEG;
#pragma unroll
        for (int nt = 0; nt < 4; nt++) {
            int jjb = ch * 32 + nt * 8 + la2;
            int jc = j0 + jjb;
            float s0 = C[nt][0] + __half2float(sG[gr0 * 130 + (jjb - gr0 + 63)]);
            float s1 = C[nt][1] + __half2float(sG[gr0 * 130 + (jjb + 1 - gr0 + 63)]);
            float s2 = C[nt][2] + __half2float(sG[(gr0 + 8) * 130 + (jjb - gr0 - 8 + 63)]);
            float s3 = C[nt][3] + __half2float(sG[(gr0 + 8) * 130 + (jjb + 1 - gr0 - 8 + 63)]);
            s0 = (jc < NL && !mrow0[jc])         ? s0 : NEG;
            s1 = (jc + 1 < NL && !mrow0[jc + 1]) ? s1 : NEG;
            s2 = (jc < NL && !mrow1[jc])         ? s2 : NEG;
            s3 = (jc + 1 < NL && !mrow1[jc + 1]) ? s3 : NEG;
            C[nt][0] = s0; C[nt][1] = s1; C[nt][2] = s2; C[nt][3] = s3;
            mt0 = fmaxf(mt0, fmaxf(s0, s1));
            mt1 = fmaxf(mt1, fmaxf(s2, s3));
        }
        mt0 = fmaxf(mt0, __shfl_xor_sync(0xffffffffu, mt0, 1));
        mt0 = fmaxf(mt0, __shfl_xor_sync(0xffffffffu, mt0, 2));
        mt1 = fmaxf(mt1, __shfl_xor_sync(0xffffffffu, mt1, 1));
        mt1 = fmaxf(mt1, __shfl_xor_sync(0xffffffffu, mt1, 2));

        // ---- online softmax update ----
        float m0n = fmaxf(m0, mt0), m1n = fmaxf(m1, mt1);
        float sf0 = __expf(m0 - m0n), sf1 = __expf(m1 - m1n);
        m0 = m0n; m1 = m1n;
        float rs0 = 0.f, rs1 = 0.f;
#pragma unroll
        for (int nt = 0; nt < 4; nt++) {
            float p0 = __expf(C[nt][0] - m0);
            float p1 = __expf(C[nt][1] - m0);
            float p2 = __expf(C[nt][2] - m1);
            float p3 = __expf(C[nt][3] - m1);
            C[nt][0] = p0; C[nt][1] = p1; C[nt][2] = p2; C[nt][3] = p3;
            rs0 += p0 + p1; rs1 += p2 + p3;
        }
        rs0 += __shfl_xor_sync(0xffffffffu, rs0, 1);
        rs0 += __shfl_xor_sync(0xffffffffu, rs0, 2);
        rs1 += __shfl_xor_sync(0xffffffffu, rs1, 1);
        rs1 += __shfl_xor_sync(0xffffffffu, rs1, 2);
        l0 = l0 * sf0 + rs0;
        l1 = l1 * sf1 + rs1;
#pragma unroll
        for (int n = 0; n < 8; n++) {
            O[n][0] *= sf0; O[n][1] *= sf0;
            O[n][2] *= sf1; O[n][3] *= sf1;
        }
        // ---- AV MMA: exp(S) frags from registers ----
#pragma unroll
        for (int s2 = 0; s2 < 2; s2++) {
            uint4 af = make_uint4(
                pkh2f(C[2 * s2][0], C[2 * s2][1]),
                pkh2f(C[2 * s2][2], C[2 * s2][3]),
                pkh2f(C[2 * s2 + 1][0], C[2 * s2 + 1][1]),
                pkh2f(C[2 * s2 + 1][2], C[2 * s2 + 1][3]));
#pragma unroll
            for (int n = 0; n < 8; n++) {
                uint2 bv = *(const uint2*)&sV[(ch * 2 + s2) * 520 + n * 64 + lam * 2];
                mma_f16(O[n], af, bv);
            }
        }
    }

    // ===================== split-k merge across ch pairs =====================
    __syncthreads();
    if (ch == 1) {
#pragma unroll
        for (int n = 0; n < 8; n++) {
            int hd = n * 8 + la2;
            *(float2*)&mO[gr0 * 68 + hd]       = make_float2(O[n][0], O[n][1]);
            *(float2*)&mO[(gr0 + 8) * 68 + hd] = make_float2(O[n][2], O[n][3]);
        }
        if ((lam & 3) == 0) {
            mml[gr0 * 2 + 0] = m0; mml[gr0 * 2 + 1] = l0;
            mml[(gr0 + 8) * 2 + 0] = m1; mml[(gr0 + 8) * 2 + 1] = l1;
        }
    }
    __syncthreads();
    if (ch == 0) {
        float ma = mml[gr0 * 2 + 0], la = mml[gr0 * 2 + 1];
        float mt = fmaxf(m0, ma);
        float e0 = __expf(m0 - mt), e1 = __expf(ma - mt);
        float inv0 = 1.f / (l0 * e0 + la * e1);
        float mb = mml[(gr0 + 8) * 2 + 0], lb = mml[(gr0 + 8) * 2 + 1];
        float mtb = fmaxf(m1, mb);
        float f0 = __expf(m1 - mtb), f1 = __expf(mb - mtb);
        float inv1 = 1.f / (l1 * f0 + lb * f1);
#pragma unroll
        for (int n = 0; n < 8; n++) {
            int hd = n * 8 + la2;
            if (r0g < NL) {
                float2 oc = *(float2*)&mO[gr0 * 68 + hd];
                *(unsigned*)&ctx[((size_t)b * NL + r0g) * ND + h * 64 + hd] =
                    pkh2f((O[n][0] * e0 + oc.x * e1) * inv0,
                          (O[n][1] * e0 + oc.y * e1) * inv0);
            }
            if (r1g < NL) {
                float2 oc = *(float2*)&mO[(gr0 + 8) * 68 + hd];
                *(unsigned*)&ctx[((size_t)b * NL + r1g) * ND + h * 64 + hd] =
                    pkh2f((O[n][2] * f0 + oc.x * f1) * inv1,
                          (O[n][3] * f0 + oc.y * f1) * inv1);
            }
        }
    }
}

// ---------------------------------------------------------------------------
extern "C" void kernel_launch(void* const* d_in, const int* in_sizes, int n_in,
                              void* d_out, int out_size)
{
    const float* x     = (const float*)d_in[0];
    const float* pe    = (const float*)d_in[1];
    const unsigned char* mask = (const unsigned char*)d_in[2];
    const float* qkv_w = (const float*)d_in[3];
    const float* qkv_b = (const float*)d_in[4];
    const float* pos_w = (const float*)d_in[5];
    const float* pos_b = (const float*)d_in[6];
    const float* out_w = (const float*)d_in[7];
    const float* out_b = (const float*)d_in[8];
    const float* cbias = (const float*)d_in[9];
    const float* pbias = (const float*)d_in[10];
    float* out = (float*)d_out;

    __half* ctxh = nullptr;
    cudaGetSymbolAddress((void**)&ctxh, g_CTXh);

    const int M1 = NB * NL;                        // 8208
    const int GEMM_SMEM = 8 * 2560 * 4;            // 81,920 B
    const int ATTN_SMEM = 12416 * 4;               // 49,664 B
    cudaFuncSetAttribute(gemm_fused, cudaFuncAttributeMaxDynamicSharedMemorySize, GEMM_SMEM);
    cudaFuncSetAttribute(gemm_out,   cudaFuncAttributeMaxDynamicSharedMemorySize, GEMM_SMEM);
    cudaFuncSetAttribute(attn_flash, cudaFuncAttributeMaxDynamicSharedMemorySize, ATTN_SMEM);

    dim3 blk(256);
    cvt_all<<<1184, 256>>>(x, qkv_w, pos_w, pe, out_w);
    gemm_fused<<<2584, blk, GEMM_SMEM>>>(qkv_b, cbias, pbias, pos_b);
    attn_flash<<<dim3(9, NH, NB), blk, ATTN_SMEM>>>(mask, ctxh);
    gemm_out<<<dim3(1024 / 128, (M1 + 127) / 128), blk, GEMM_SMEM>>>(M1, out_b, out);
}